// round 9
// baseline (speedup 1.0000x reference)
#include <cuda_runtime.h>
#include <cuda_bf16.h>

// Problem constants
#define BATCH   4
#define LENGTH  512
#define DMODEL  128
#define DINNER  256
#define DSTATE  256
#define MROWS   (BATCH * LENGTH)        // 2048
#define LOG2E   1.4426950408889634f
#define NC      16                      // scan chunks
#define TC      32                      // steps per chunk (NC*TC == LENGTH)

// Scratch (allocation-free: __device__ globals)
__device__ float g_xs[MROWS * DINNER];     // xs (first half of in_proj)
__device__ float g_sz[MROWS * DINNER];     // silu(z)
__device__ float g_delta[MROWS * DINNER];  // xs @ W_delta
__device__ float g_bu[MROWS * DSTATE];     // (xs @ W_B) * xs   (elementwise)
__device__ float g_Cv[MROWS * DINNER];     // xs @ W_C
__device__ float g_y[MROWS * DINNER];      // scan output * silu(z)

// Chunked-scan intermediates: layout [((b*NC + c)*256 + d)*256 + n]
__device__ float g_P  [BATCH * NC * DINNER * DSTATE];  // per-chunk prod of a_t
__device__ float g_Sf [BATCH * NC * DINNER * DSTATE];  // per-chunk local final state
__device__ float g_Sin[BATCH * NC * DINNER * DSTATE];  // per-chunk initial state

__device__ __forceinline__ float ex2f(float x) {
    float e; asm("ex2.approx.ftz.f32 %0, %1;" : "=f"(e) : "f"(x)); return e;
}

// ---------------------------------------------------------------------------
// Tiled fp32 GEMM: C tile 32x64 per block, 128 threads, thread tile 4x4.
// ---------------------------------------------------------------------------
template <int MODE>
__global__ __launch_bounds__(128)
void gemm_kernel(const float* __restrict__ Ag_,
                 const float* __restrict__ B0,
                 const float* __restrict__ B1,
                 const float* __restrict__ B2,
                 float* __restrict__ Og)
{
    constexpr int K   = (MODE == 0) ? 128 : 256;
    constexpr int LDB = (MODE == 0) ? 512 : ((MODE == 1) ? 256 : 128);

    __shared__ float As[16][36];
    __shared__ float Bs[16][68];

    const int tid = threadIdx.x;
    const int tx  = tid & 15;
    const int ty  = tid >> 4;
    const int m0  = blockIdx.y * 32;

    const float* Ag;
    const float* Bg;
    int n0;
    int which = 0;
    if (MODE == 1) {
        which = blockIdx.x >> 2;              // 0: W_delta, 1: W_B, 2: W_C
        n0 = (blockIdx.x & 3) * 64;
        Bg = (which == 0) ? B0 : ((which == 1) ? B1 : B2);
        Ag = g_xs;
    } else {
        n0 = blockIdx.x * 64;
        Bg = B0;
        Ag = (MODE == 0) ? Ag_ : g_y;
    }

    const int aRow  = tid >> 2;
    const int aC4   = (tid & 3) << 2;
    const int bRowk = tid >> 4;
    const int bC4   = (tid & 15) << 2;

    float4 aR;
    float4 bR[2];
    aR = *(const float4*)(Ag + (size_t)(m0 + aRow) * K + aC4);
#pragma unroll
    for (int r = 0; r < 2; r++)
        bR[r] = *(const float4*)(Bg + (size_t)(bRowk + r * 8) * LDB + n0 + bC4);

    float acc[4][4];
#pragma unroll
    for (int i = 0; i < 4; i++)
#pragma unroll
        for (int j = 0; j < 4; j++) acc[i][j] = 0.f;

    for (int k0 = 0; k0 < K; k0 += 16) {
        As[aC4 + 0][aRow] = aR.x;
        As[aC4 + 1][aRow] = aR.y;
        As[aC4 + 2][aRow] = aR.z;
        As[aC4 + 3][aRow] = aR.w;
#pragma unroll
        for (int r = 0; r < 2; r++)
            *(float4*)&Bs[bRowk + r * 8][bC4] = bR[r];
        __syncthreads();

        if (k0 + 16 < K) {
            aR = *(const float4*)(Ag + (size_t)(m0 + aRow) * K + (k0 + 16) + aC4);
#pragma unroll
            for (int r = 0; r < 2; r++)
                bR[r] = *(const float4*)(Bg + (size_t)(k0 + 16 + bRowk + r * 8) * LDB + n0 + bC4);
        }

#pragma unroll
        for (int kk = 0; kk < 16; kk++) {
            float4 av = *(const float4*)&As[kk][ty * 4];
            float4 bv = *(const float4*)&Bs[kk][tx * 4];
            float a[4] = {av.x, av.y, av.z, av.w};
            float b[4] = {bv.x, bv.y, bv.z, bv.w};
#pragma unroll
            for (int i = 0; i < 4; i++)
#pragma unroll
                for (int j = 0; j < 4; j++)
                    acc[i][j] = fmaf(a[i], b[j], acc[i][j]);
        }
        __syncthreads();
    }

#pragma unroll
    for (int i = 0; i < 4; i++) {
        int m = m0 + ty * 4 + i;
#pragma unroll
        for (int j = 0; j < 4; j++) {
            int c = n0 + tx * 4 + j;
            float v = acc[i][j];
            if (MODE == 0) {
                if (c < 256) {
                    g_xs[m * 256 + c] = v;
                } else {
                    float sig = 1.f / (1.f + __expf(-v));
                    g_sz[m * 256 + (c - 256)] = v * sig;   // silu(z)
                }
            } else if (MODE == 1) {
                if (which == 0)      g_delta[m * 256 + c] = v;
                else if (which == 1) g_bu[m * 256 + c] = v * g_xs[m * 256 + c];
                else                 g_Cv[m * 256 + c] = v;
            } else {
                Og[m * 128 + c] = v;
            }
        }
    }
}

// ---------------------------------------------------------------------------
// Scan pass 1: chunks 0..NC-2. Each WARP handles 2 consecutive d's.
//   Sf = local final state (zero-init recurrence)
//   P  = exp2(Ae * sum_chunk delta)   (separable exact product of per-step e's)
// ---------------------------------------------------------------------------
__global__ __launch_bounds__(128, 8)
void scan_p1(const float* __restrict__ A)
{
    const int warp = threadIdx.x >> 5;
    const int lane = threadIdx.x & 31;
    int bid = blockIdx.x;                  // ((c*BATCH + b)*32 + dblk)
    const int dblk = bid & 31;  bid >>= 5;
    const int b    = bid & 3;   bid >>= 2;
    const int c    = bid;                  // 0 .. NC-2
    const int d0   = (dblk * 4 + warp) * 2;
    const int nb   = lane << 3;

    float Ae[2][8];
#pragma unroll
    for (int di = 0; di < 2; di++)
#pragma unroll
        for (int j = 0; j < 8; j++)
            Ae[di][j] = A[(d0 + di) * 256 + nb + j] * LOG2E;

    const int base = b * LENGTH * 256;
    const float* __restrict__ bu = g_bu    + base;
    const float* __restrict__ dp = g_delta + base;

    float s[2][8], dsum[2];
#pragma unroll
    for (int di = 0; di < 2; di++) {
        dsum[di] = 0.f;
#pragma unroll
        for (int j = 0; j < 8; j++) s[di][j] = 0.f;
    }

    const int t0 = c * TC;
    for (int t = t0; t < t0 + TC; t++) {
        float2 d2 = *(const float2*)(dp + t * 256 + d0);
        float del[2] = {d2.x, d2.y};
        float buv[8];
        *(float4*)&buv[0] = *(const float4*)(bu + t * 256 + nb);
        *(float4*)&buv[4] = *(const float4*)(bu + t * 256 + nb + 4);
#pragma unroll
        for (int di = 0; di < 2; di++) {
            dsum[di] += del[di];
#pragma unroll
            for (int j = 0; j < 8; j++) {
                float e = ex2f(del[di] * Ae[di][j]);
                s[di][j] = fmaf(e, s[di][j], del[di] * buv[j]);
            }
        }
    }

#pragma unroll
    for (int di = 0; di < 2; di++) {
        float P[8];
#pragma unroll
        for (int j = 0; j < 8; j++)
            P[j] = ex2f(dsum[di] * Ae[di][j]);
        const size_t o = ((size_t)((b * NC + c) * 256 + d0 + di)) * 256 + nb;
        *(float4*)(g_P  + o)     = *(float4*)&P[0];
        *(float4*)(g_P  + o + 4) = *(float4*)&P[4];
        *(float4*)(g_Sf + o)     = *(float4*)&s[di][0];
        *(float4*)(g_Sf + o + 4) = *(float4*)&s[di][4];
    }
}

// ---------------------------------------------------------------------------
// Chunk-summary scan (separate kernel, float4-vectorized, perfectly
// coalesced, O(NC) traffic): per (b,d,n4): Sin[c+1] = P[c]*Sin[c] + Sf[c].
// Doing this once here (instead of O(NC^2/2) re-scans inside p2's prologue)
// removes ~1.6M L1 wavefronts from p2 AND makes all p2 blocks equal-length.
// ---------------------------------------------------------------------------
__global__ __launch_bounds__(256)
void chunk_scan()
{
    const int i   = blockIdx.x * 256 + threadIdx.x;   // float4 index
    const int b   = i >> 14;                          // 16384 float4 per batch
    const int dn4 = i & 16383;

    float4 S = make_float4(0.f, 0.f, 0.f, 0.f);
#pragma unroll
    for (int c = 0; c < NC - 1; c++) {
        const size_t o4 = ((size_t)(b * NC + c) << 14) + dn4;
        float4 P  = ((const float4*)g_P )[o4];
        float4 Sf = ((const float4*)g_Sf)[o4];
        S.x = fmaf(P.x, S.x, Sf.x);
        S.y = fmaf(P.y, S.y, Sf.y);
        S.z = fmaf(P.z, S.z, Sf.z);
        S.w = fmaf(P.w, S.w, Sf.w);
        ((float4*)g_Sin)[o4 + 16384] = S;   // slot c+1
    }
}

// ---------------------------------------------------------------------------
// Scan pass 2: each WARP handles 2 consecutive d's; initial state is a
// single Sin load (all blocks equal-length). bu/cv prefetched by one step.
// 6-shfl reduction; lane 0 / lane 16 store y*silu(z) for d0 / d0+1.
// ---------------------------------------------------------------------------
__global__ __launch_bounds__(128, 6)
void scan_p2(const float* __restrict__ A)
{
    const int warp = threadIdx.x >> 5;
    const int lane = threadIdx.x & 31;
    int bid = blockIdx.x;                  // ((c*BATCH + b)*32 + dblk)
    const int dblk = bid & 31;  bid >>= 5;
    const int b    = bid & 3;   bid >>= 2;
    const int c    = bid;                  // 0 .. NC-1
    const int d0   = (dblk * 4 + warp) * 2;
    const int nb   = lane << 3;

    float Ae[2][8];
#pragma unroll
    for (int di = 0; di < 2; di++)
#pragma unroll
        for (int j = 0; j < 8; j++)
            Ae[di][j] = A[(d0 + di) * 256 + nb + j] * LOG2E;

    // Initial state: one coalesced Sin load (c==0 -> zeros)
    float s[2][8];
    if (c == 0) {
#pragma unroll
        for (int di = 0; di < 2; di++)
#pragma unroll
            for (int j = 0; j < 8; j++) s[di][j] = 0.f;
    } else {
#pragma unroll
        for (int di = 0; di < 2; di++) {
            const size_t o = ((size_t)((b * NC + c) * 256 + d0 + di)) * 256 + nb;
            *(float4*)&s[di][0] = *(const float4*)(g_Sin + o);
            *(float4*)&s[di][4] = *(const float4*)(g_Sin + o + 4);
        }
    }

    const int base = b * LENGTH * 256;
    const float* __restrict__ bu  = g_bu    + base;
    const float* __restrict__ Cp  = g_Cv    + base;
    const float* __restrict__ dp  = g_delta + base;
    const float* __restrict__ szp = g_sz    + base;
    float*       __restrict__ yp  = g_y     + base;

    const int t0 = c * TC, t1 = t0 + TC;

    float buv[8], cv[8];
    *(float4*)&buv[0] = *(const float4*)(bu + t0 * 256 + nb);
    *(float4*)&buv[4] = *(const float4*)(bu + t0 * 256 + nb + 4);
    *(float4*)&cv[0]  = *(const float4*)(Cp + t0 * 256 + nb);
    *(float4*)&cv[4]  = *(const float4*)(Cp + t0 * 256 + nb + 4);

    for (int t = t0; t < t1; t++) {
        // prefetch next step's bu/cv (delta is an L1-hit broadcast, no need)
        const int tn = (t + 1 < t1) ? t + 1 : t;
        float bun[8], cvn[8];
        *(float4*)&bun[0] = *(const float4*)(bu + tn * 256 + nb);
        *(float4*)&bun[4] = *(const float4*)(bu + tn * 256 + nb + 4);
        *(float4*)&cvn[0] = *(const float4*)(Cp + tn * 256 + nb);
        *(float4*)&cvn[4] = *(const float4*)(Cp + tn * 256 + nb + 4);

        float2 d2 = *(const float2*)(dp + t * 256 + d0);
        float del[2] = {d2.x, d2.y};

        float y[2];
#pragma unroll
        for (int di = 0; di < 2; di++) {
            float yacc = 0.f;
#pragma unroll
            for (int j = 0; j < 8; j++) {
                float e = ex2f(del[di] * Ae[di][j]);
                s[di][j] = fmaf(e, s[di][j], del[di] * buv[j]);
                yacc = fmaf(s[di][j], cv[j], yacc);
            }
            y[di] = yacc;
        }

        // 6-shfl reduction: xor16 both -> halves own one d each -> xor8/4/2/1
        y[0] += __shfl_xor_sync(0xffffffffu, y[0], 16);
        y[1] += __shfl_xor_sync(0xffffffffu, y[1], 16);
        float v = (lane < 16) ? y[0] : y[1];
        v += __shfl_xor_sync(0xffffffffu, v, 8);
        v += __shfl_xor_sync(0xffffffffu, v, 4);
        v += __shfl_xor_sync(0xffffffffu, v, 2);
        v += __shfl_xor_sync(0xffffffffu, v, 1);
        if (lane == 0)
            yp[t * 256 + d0]     = v * szp[t * 256 + d0];
        if (lane == 16)
            yp[t * 256 + d0 + 1] = v * szp[t * 256 + d0 + 1];

#pragma unroll
        for (int j = 0; j < 8; j++) { buv[j] = bun[j]; cv[j] = cvn[j]; }
    }
}

// ---------------------------------------------------------------------------
// Inputs (metadata order): x, W_in, W_delta, W_B, W_C, W_out, A, D(unused)
// ---------------------------------------------------------------------------
extern "C" void kernel_launch(void* const* d_in, const int* in_sizes, int n_in,
                              void* d_out, int out_size)
{
    const float* x       = (const float*)d_in[0];
    const float* W_in    = (const float*)d_in[1];
    const float* W_delta = (const float*)d_in[2];
    const float* W_B     = (const float*)d_in[3];
    const float* W_C     = (const float*)d_in[4];
    const float* W_out   = (const float*)d_in[5];
    const float* A       = (const float*)d_in[6];
    float* out = (float*)d_out;

    // 1) in_proj + split + silu(z)
    gemm_kernel<0><<<dim3(8, 64), 128>>>(x, W_in, nullptr, nullptr, nullptr);
    // 2) delta / bu / Cv projections (fused triple GEMM)
    gemm_kernel<1><<<dim3(12, 64), 128>>>(nullptr, W_delta, W_B, W_C, nullptr);
    // 3) chunked selective scan
    scan_p1<<<(NC - 1) * BATCH * 32, 128>>>(A);
    chunk_scan<<<(BATCH * DINNER * DSTATE) / 1024, 256>>>();
    scan_p2<<<NC * BATCH * 32, 128>>>(A);
    // 4) out_proj
    gemm_kernel<2><<<dim3(2, 64), 128>>>(nullptr, W_out, nullptr, nullptr, out);
}

// round 12
// speedup vs baseline: 1.0050x; 1.0050x over previous
#include <cuda_runtime.h>
#include <cuda_bf16.h>

// Problem constants
#define BATCH   4
#define LENGTH  512
#define DMODEL  128
#define DINNER  256
#define DSTATE  256
#define MROWS   (BATCH * LENGTH)        // 2048
#define LOG2E   1.4426950408889634f
#define NC      16                      // scan chunks
#define TC      32                      // steps per chunk (NC*TC == LENGTH)

// Scratch (allocation-free: __device__ globals)
__device__ float g_xs[MROWS * DINNER];     // xs (first half of in_proj)
__device__ float g_sz[MROWS * DINNER];     // silu(z)
__device__ float g_delta[MROWS * DINNER];  // xs @ W_delta
__device__ float g_bu[MROWS * DSTATE];     // (xs @ W_B) * xs   (elementwise)
__device__ float g_Cv[MROWS * DINNER];     // xs @ W_C
__device__ float g_y[MROWS * DINNER];      // scan output * silu(z)

// Chunked-scan intermediates: layout [((b*NC + c)*256 + d)*256 + n]
__device__ float g_P  [BATCH * NC * DINNER * DSTATE];  // per-chunk prod of a_t
__device__ float g_Sf [BATCH * NC * DINNER * DSTATE];  // per-chunk local final state

__device__ __forceinline__ float ex2f(float x) {
    float e; asm("ex2.approx.ftz.f32 %0, %1;" : "=f"(e) : "f"(x)); return e;
}

// ---------------------------------------------------------------------------
// Tiled fp32 GEMM: C tile 32x64 per block, 128 threads, thread tile 4x4.
// ---------------------------------------------------------------------------
template <int MODE>
__global__ __launch_bounds__(128)
void gemm_kernel(const float* __restrict__ Ag_,
                 const float* __restrict__ B0,
                 const float* __restrict__ B1,
                 const float* __restrict__ B2,
                 float* __restrict__ Og)
{
    constexpr int K   = (MODE == 0) ? 128 : 256;
    constexpr int LDB = (MODE == 0) ? 512 : ((MODE == 1) ? 256 : 128);

    __shared__ float As[16][36];
    __shared__ float Bs[16][68];

    const int tid = threadIdx.x;
    const int tx  = tid & 15;
    const int ty  = tid >> 4;
    const int m0  = blockIdx.y * 32;

    const float* Ag;
    const float* Bg;
    int n0;
    int which = 0;
    if (MODE == 1) {
        which = blockIdx.x >> 2;              // 0: W_delta, 1: W_B, 2: W_C
        n0 = (blockIdx.x & 3) * 64;
        Bg = (which == 0) ? B0 : ((which == 1) ? B1 : B2);
        Ag = g_xs;
    } else {
        n0 = blockIdx.x * 64;
        Bg = B0;
        Ag = (MODE == 0) ? Ag_ : g_y;
    }

    const int aRow  = tid >> 2;
    const int aC4   = (tid & 3) << 2;
    const int bRowk = tid >> 4;
    const int bC4   = (tid & 15) << 2;

    float4 aR;
    float4 bR[2];
    aR = *(const float4*)(Ag + (size_t)(m0 + aRow) * K + aC4);
#pragma unroll
    for (int r = 0; r < 2; r++)
        bR[r] = *(const float4*)(Bg + (size_t)(bRowk + r * 8) * LDB + n0 + bC4);

    float acc[4][4];
#pragma unroll
    for (int i = 0; i < 4; i++)
#pragma unroll
        for (int j = 0; j < 4; j++) acc[i][j] = 0.f;

    for (int k0 = 0; k0 < K; k0 += 16) {
        As[aC4 + 0][aRow] = aR.x;
        As[aC4 + 1][aRow] = aR.y;
        As[aC4 + 2][aRow] = aR.z;
        As[aC4 + 3][aRow] = aR.w;
#pragma unroll
        for (int r = 0; r < 2; r++)
            *(float4*)&Bs[bRowk + r * 8][bC4] = bR[r];
        __syncthreads();

        if (k0 + 16 < K) {
            aR = *(const float4*)(Ag + (size_t)(m0 + aRow) * K + (k0 + 16) + aC4);
#pragma unroll
            for (int r = 0; r < 2; r++)
                bR[r] = *(const float4*)(Bg + (size_t)(k0 + 16 + bRowk + r * 8) * LDB + n0 + bC4);
        }

#pragma unroll
        for (int kk = 0; kk < 16; kk++) {
            float4 av = *(const float4*)&As[kk][ty * 4];
            float4 bv = *(const float4*)&Bs[kk][tx * 4];
            float a[4] = {av.x, av.y, av.z, av.w};
            float b[4] = {bv.x, bv.y, bv.z, bv.w};
#pragma unroll
            for (int i = 0; i < 4; i++)
#pragma unroll
                for (int j = 0; j < 4; j++)
                    acc[i][j] = fmaf(a[i], b[j], acc[i][j]);
        }
        __syncthreads();
    }

#pragma unroll
    for (int i = 0; i < 4; i++) {
        int m = m0 + ty * 4 + i;
#pragma unroll
        for (int j = 0; j < 4; j++) {
            int c = n0 + tx * 4 + j;
            float v = acc[i][j];
            if (MODE == 0) {
                if (c < 256) {
                    g_xs[m * 256 + c] = v;
                } else {
                    float sig = 1.f / (1.f + __expf(-v));
                    g_sz[m * 256 + (c - 256)] = v * sig;   // silu(z)
                }
            } else if (MODE == 1) {
                if (which == 0)      g_delta[m * 256 + c] = v;
                else if (which == 1) g_bu[m * 256 + c] = v * g_xs[m * 256 + c];
                else                 g_Cv[m * 256 + c] = v;
            } else {
                Og[m * 128 + c] = v;
            }
        }
    }
}

// ---------------------------------------------------------------------------
// Scan pass 1: chunks 0..NC-2. 256-thread blocks (8 warps x 2 d's = 16 d's).
// grid = 960 < single-wave concurrency (148 SMs x 4 blocks) -> no wave tail.
//   Sf = local final state (zero-init recurrence)
//   P  = exp2(Ae * sum_chunk delta)
// ---------------------------------------------------------------------------
__global__ __launch_bounds__(256, 4)
void scan_p1(const float* __restrict__ A)
{
    const int warp = threadIdx.x >> 5;     // 0..7
    const int lane = threadIdx.x & 31;
    // bid = (dblk*BATCH + b)*(NC-1) + c  -> c varies fastest (mix block lengths)
    int bid = blockIdx.x;
    const int c    = bid % (NC - 1);
    bid /= (NC - 1);
    const int b    = bid & 3;
    const int dblk = bid >> 2;             // 0..15
    const int d0   = (dblk * 8 + warp) * 2;
    const int nb   = lane << 3;

    float Ae[2][8];
#pragma unroll
    for (int di = 0; di < 2; di++)
#pragma unroll
        for (int j = 0; j < 8; j++)
            Ae[di][j] = A[(d0 + di) * 256 + nb + j] * LOG2E;

    const int base = b * LENGTH * 256;
    const float* __restrict__ bu = g_bu    + base;
    const float* __restrict__ dp = g_delta + base;

    float s[2][8], dsum[2];
#pragma unroll
    for (int di = 0; di < 2; di++) {
        dsum[di] = 0.f;
#pragma unroll
        for (int j = 0; j < 8; j++) s[di][j] = 0.f;
    }

    const int t0 = c * TC;
    for (int t = t0; t < t0 + TC; t++) {
        float2 d2 = *(const float2*)(dp + t * 256 + d0);
        float del[2] = {d2.x, d2.y};
        float buv[8];
        *(float4*)&buv[0] = *(const float4*)(bu + t * 256 + nb);
        *(float4*)&buv[4] = *(const float4*)(bu + t * 256 + nb + 4);
#pragma unroll
        for (int di = 0; di < 2; di++) {
            dsum[di] += del[di];
#pragma unroll
            for (int j = 0; j < 8; j++) {
                float e = ex2f(del[di] * Ae[di][j]);
                s[di][j] = fmaf(e, s[di][j], del[di] * buv[j]);
            }
        }
    }

#pragma unroll
    for (int di = 0; di < 2; di++) {
        float P[8];
#pragma unroll
        for (int j = 0; j < 8; j++)
            P[j] = ex2f(dsum[di] * Ae[di][j]);
        const size_t o = ((size_t)((b * NC + c) * 256 + d0 + di)) * 256 + nb;
        *(float4*)(g_P  + o)     = *(float4*)&P[0];
        *(float4*)(g_P  + o + 4) = *(float4*)&P[4];
        *(float4*)(g_Sf + o)     = *(float4*)&s[di][0];
        *(float4*)(g_Sf + o + 4) = *(float4*)&s[di][4];
    }
}

// ---------------------------------------------------------------------------
// Scan pass 2 (fused chunk-summary prologue). 256-thread blocks, 8 warps x
// 2 d's. grid = 1024 < single-wave concurrency -> no wave tail; c varies
// fastest in bid so each SM gets a mix of short/long prologue blocks.
// 6-shfl reduction; lane 0 / lane 16 store y*silu(z) for d0 / d0+1.
// ---------------------------------------------------------------------------
__global__ __launch_bounds__(256, 4)
void scan_p2(const float* __restrict__ A)
{
    const int warp = threadIdx.x >> 5;
    const int lane = threadIdx.x & 31;
    // bid = (dblk*BATCH + b)*NC + c  -> c fastest
    int bid = blockIdx.x;
    const int c    = bid & 15;
    bid >>= 4;
    const int b    = bid & 3;
    const int dblk = bid >> 2;             // 0..15
    const int d0   = (dblk * 8 + warp) * 2;
    const int nb   = lane << 3;

    float Ae[2][8];
#pragma unroll
    for (int di = 0; di < 2; di++)
#pragma unroll
        for (int j = 0; j < 8; j++)
            Ae[di][j] = A[(d0 + di) * 256 + nb + j] * LOG2E;

    // Reconstruct initial states from chunks 0..c-1 (L2-resident, overlapped)
    float s[2][8];
#pragma unroll
    for (int di = 0; di < 2; di++)
#pragma unroll
        for (int j = 0; j < 8; j++) s[di][j] = 0.f;
    for (int cc = 0; cc < c; cc++) {
#pragma unroll
        for (int di = 0; di < 2; di++) {
            const size_t o = ((size_t)((b * NC + cc) * 256 + d0 + di)) * 256 + nb;
            float P[8], Sf[8];
            *(float4*)&P[0]  = *(const float4*)(g_P  + o);
            *(float4*)&P[4]  = *(const float4*)(g_P  + o + 4);
            *(float4*)&Sf[0] = *(const float4*)(g_Sf + o);
            *(float4*)&Sf[4] = *(const float4*)(g_Sf + o + 4);
#pragma unroll
            for (int j = 0; j < 8; j++)
                s[di][j] = fmaf(P[j], s[di][j], Sf[j]);
        }
    }

    const int base = b * LENGTH * 256;
    const float* __restrict__ bu  = g_bu    + base;
    const float* __restrict__ Cp  = g_Cv    + base;
    const float* __restrict__ dp  = g_delta + base;
    const float* __restrict__ szp = g_sz    + base;
    float*       __restrict__ yp  = g_y     + base;

    const int t0 = c * TC;
    for (int t = t0; t < t0 + TC; t++) {
        float2 d2 = *(const float2*)(dp + t * 256 + d0);
        float del[2] = {d2.x, d2.y};
        float buv[8], cv[8];
        *(float4*)&buv[0] = *(const float4*)(bu + t * 256 + nb);
        *(float4*)&buv[4] = *(const float4*)(bu + t * 256 + nb + 4);
        *(float4*)&cv[0]  = *(const float4*)(Cp + t * 256 + nb);
        *(float4*)&cv[4]  = *(const float4*)(Cp + t * 256 + nb + 4);

        float y[2];
#pragma unroll
        for (int di = 0; di < 2; di++) {
            float yacc = 0.f;
#pragma unroll
            for (int j = 0; j < 8; j++) {
                float e = ex2f(del[di] * Ae[di][j]);
                s[di][j] = fmaf(e, s[di][j], del[di] * buv[j]);
                yacc = fmaf(s[di][j], cv[j], yacc);
            }
            y[di] = yacc;
        }

        // 6-shfl reduction: xor16 both -> halves own one d each -> xor8/4/2/1
        y[0] += __shfl_xor_sync(0xffffffffu, y[0], 16);
        y[1] += __shfl_xor_sync(0xffffffffu, y[1], 16);
        float v = (lane < 16) ? y[0] : y[1];
        v += __shfl_xor_sync(0xffffffffu, v, 8);
        v += __shfl_xor_sync(0xffffffffu, v, 4);
        v += __shfl_xor_sync(0xffffffffu, v, 2);
        v += __shfl_xor_sync(0xffffffffu, v, 1);
        // lane 0 holds y[d0], lane 16 holds y[d0+1] — store directly
        if (lane == 0)
            yp[t * 256 + d0]     = v * szp[t * 256 + d0];
        if (lane == 16)
            yp[t * 256 + d0 + 1] = v * szp[t * 256 + d0 + 1];
    }
}

// ---------------------------------------------------------------------------
// Inputs (metadata order): x, W_in, W_delta, W_B, W_C, W_out, A, D(unused)
// ---------------------------------------------------------------------------
extern "C" void kernel_launch(void* const* d_in, const int* in_sizes, int n_in,
                              void* d_out, int out_size)
{
    const float* x       = (const float*)d_in[0];
    const float* W_in    = (const float*)d_in[1];
    const float* W_delta = (const float*)d_in[2];
    const float* W_B     = (const float*)d_in[3];
    const float* W_C     = (const float*)d_in[4];
    const float* W_out   = (const float*)d_in[5];
    const float* A       = (const float*)d_in[6];
    float* out = (float*)d_out;

    // 1) in_proj + split + silu(z)
    gemm_kernel<0><<<dim3(8, 64), 128>>>(x, W_in, nullptr, nullptr, nullptr);
    // 2) delta / bu / Cv projections (fused triple GEMM)
    gemm_kernel<1><<<dim3(12, 64), 128>>>(nullptr, W_delta, W_B, W_C, nullptr);
    // 3) chunked selective scan (single-wave grids, c-interleaved block order)
    scan_p1<<<(NC - 1) * BATCH * 16, 256>>>(A);
    scan_p2<<<NC * BATCH * 16, 256>>>(A);
    // 4) out_proj
    gemm_kernel<2><<<dim3(2, 64), 128>>>(nullptr, W_out, nullptr, nullptr, out);
}

// round 13
// speedup vs baseline: 1.0138x; 1.0088x over previous
#include <cuda_runtime.h>
#include <cuda_bf16.h>

// Problem constants
#define BATCH   4
#define LENGTH  512
#define DMODEL  128
#define DINNER  256
#define DSTATE  256
#define MROWS   (BATCH * LENGTH)        // 2048
#define LOG2E   1.4426950408889634f
#define NC      16                      // scan chunks
#define TC      32                      // steps per chunk (NC*TC == LENGTH)

// Scratch (allocation-free: __device__ globals)
__device__ float g_xs[MROWS * DINNER];     // xs (first half of in_proj)
__device__ float g_sz[MROWS * DINNER];     // silu(z)
__device__ float g_delta[MROWS * DINNER];  // xs @ W_delta
__device__ float g_bu[MROWS * DSTATE];     // (xs @ W_B) * xs   (elementwise)
__device__ float g_Cv[MROWS * DINNER];     // xs @ W_C
__device__ float g_y[MROWS * DINNER];      // scan output * silu(z)

// Chunked-scan intermediates: layout [((b*NC + c)*256 + d)*256 + n]
__device__ float g_P  [BATCH * NC * DINNER * DSTATE];  // per-chunk prod of a_t
__device__ float g_Sf [BATCH * NC * DINNER * DSTATE];  // per-chunk local final state

__device__ __forceinline__ float ex2f(float x) {
    float e; asm("ex2.approx.ftz.f32 %0, %1;" : "=f"(e) : "f"(x)); return e;
}
// Zero-register L1 prefetch: one warp-op covers the whole row (lines dedup).
__device__ __forceinline__ void pfL1(const float* p) {
    asm volatile("prefetch.global.L1 [%0];" :: "l"(p));
}

// ---------------------------------------------------------------------------
// Tiled fp32 GEMM: C tile 32x64 per block, 128 threads, thread tile 4x4.
// ---------------------------------------------------------------------------
template <int MODE>
__global__ __launch_bounds__(128)
void gemm_kernel(const float* __restrict__ Ag_,
                 const float* __restrict__ B0,
                 const float* __restrict__ B1,
                 const float* __restrict__ B2,
                 float* __restrict__ Og)
{
    constexpr int K   = (MODE == 0) ? 128 : 256;
    constexpr int LDB = (MODE == 0) ? 512 : ((MODE == 1) ? 256 : 128);

    __shared__ float As[16][36];
    __shared__ float Bs[16][68];

    const int tid = threadIdx.x;
    const int tx  = tid & 15;
    const int ty  = tid >> 4;
    const int m0  = blockIdx.y * 32;

    const float* Ag;
    const float* Bg;
    int n0;
    int which = 0;
    if (MODE == 1) {
        which = blockIdx.x >> 2;              // 0: W_delta, 1: W_B, 2: W_C
        n0 = (blockIdx.x & 3) * 64;
        Bg = (which == 0) ? B0 : ((which == 1) ? B1 : B2);
        Ag = g_xs;
    } else {
        n0 = blockIdx.x * 64;
        Bg = B0;
        Ag = (MODE == 0) ? Ag_ : g_y;
    }

    const int aRow  = tid >> 2;
    const int aC4   = (tid & 3) << 2;
    const int bRowk = tid >> 4;
    const int bC4   = (tid & 15) << 2;

    float4 aR;
    float4 bR[2];
    aR = *(const float4*)(Ag + (size_t)(m0 + aRow) * K + aC4);
#pragma unroll
    for (int r = 0; r < 2; r++)
        bR[r] = *(const float4*)(Bg + (size_t)(bRowk + r * 8) * LDB + n0 + bC4);

    float acc[4][4];
#pragma unroll
    for (int i = 0; i < 4; i++)
#pragma unroll
        for (int j = 0; j < 4; j++) acc[i][j] = 0.f;

    for (int k0 = 0; k0 < K; k0 += 16) {
        As[aC4 + 0][aRow] = aR.x;
        As[aC4 + 1][aRow] = aR.y;
        As[aC4 + 2][aRow] = aR.z;
        As[aC4 + 3][aRow] = aR.w;
#pragma unroll
        for (int r = 0; r < 2; r++)
            *(float4*)&Bs[bRowk + r * 8][bC4] = bR[r];
        __syncthreads();

        if (k0 + 16 < K) {
            aR = *(const float4*)(Ag + (size_t)(m0 + aRow) * K + (k0 + 16) + aC4);
#pragma unroll
            for (int r = 0; r < 2; r++)
                bR[r] = *(const float4*)(Bg + (size_t)(k0 + 16 + bRowk + r * 8) * LDB + n0 + bC4);
        }

#pragma unroll
        for (int kk = 0; kk < 16; kk++) {
            float4 av = *(const float4*)&As[kk][ty * 4];
            float4 bv = *(const float4*)&Bs[kk][tx * 4];
            float a[4] = {av.x, av.y, av.z, av.w};
            float b[4] = {bv.x, bv.y, bv.z, bv.w};
#pragma unroll
            for (int i = 0; i < 4; i++)
#pragma unroll
                for (int j = 0; j < 4; j++)
                    acc[i][j] = fmaf(a[i], b[j], acc[i][j]);
        }
        __syncthreads();
    }

#pragma unroll
    for (int i = 0; i < 4; i++) {
        int m = m0 + ty * 4 + i;
#pragma unroll
        for (int j = 0; j < 4; j++) {
            int c = n0 + tx * 4 + j;
            float v = acc[i][j];
            if (MODE == 0) {
                if (c < 256) {
                    g_xs[m * 256 + c] = v;
                } else {
                    float sig = 1.f / (1.f + __expf(-v));
                    g_sz[m * 256 + (c - 256)] = v * sig;   // silu(z)
                }
            } else if (MODE == 1) {
                if (which == 0)      g_delta[m * 256 + c] = v;
                else if (which == 1) g_bu[m * 256 + c] = v * g_xs[m * 256 + c];
                else                 g_Cv[m * 256 + c] = v;
            } else {
                Og[m * 128 + c] = v;
            }
        }
    }
}

// ---------------------------------------------------------------------------
// Scan pass 1: chunks 0..NC-2. Each WARP handles 2 consecutive d's.
// Next-step bu row is L1-prefetched (zero registers) so loads hit L1 (~39cy)
// instead of L2 (~240cy) — the diagnosed latency exposure.
//   Sf = local final state (zero-init recurrence)
//   P  = exp2(Ae * sum_chunk delta)
// ---------------------------------------------------------------------------
__global__ __launch_bounds__(128, 8)
void scan_p1(const float* __restrict__ A)
{
    const int warp = threadIdx.x >> 5;
    const int lane = threadIdx.x & 31;
    int bid = blockIdx.x;                  // ((c*BATCH + b)*32 + dblk)
    const int dblk = bid & 31;  bid >>= 5;
    const int b    = bid & 3;   bid >>= 2;
    const int c    = bid;                  // 0 .. NC-2
    const int d0   = (dblk * 4 + warp) * 2;
    const int nb   = lane << 3;

    float Ae[2][8];
#pragma unroll
    for (int di = 0; di < 2; di++)
#pragma unroll
        for (int j = 0; j < 8; j++)
            Ae[di][j] = A[(d0 + di) * 256 + nb + j] * LOG2E;

    const int base = b * LENGTH * 256;
    const float* __restrict__ bu = g_bu    + base;
    const float* __restrict__ dp = g_delta + base;

    float s[2][8], dsum[2];
#pragma unroll
    for (int di = 0; di < 2; di++) {
        dsum[di] = 0.f;
#pragma unroll
        for (int j = 0; j < 8; j++) s[di][j] = 0.f;
    }

    const int t0 = c * TC;
    pfL1(bu + t0 * 256 + nb);                        // warm first row
    for (int t = t0; t < t0 + TC; t++) {
        if (t + 1 < t0 + TC)                         // prefetch next bu row
            pfL1(bu + (t + 1) * 256 + nb);
        float2 d2 = *(const float2*)(dp + t * 256 + d0);
        float del[2] = {d2.x, d2.y};
        float buv[8];
        *(float4*)&buv[0] = *(const float4*)(bu + t * 256 + nb);
        *(float4*)&buv[4] = *(const float4*)(bu + t * 256 + nb + 4);
#pragma unroll
        for (int di = 0; di < 2; di++) {
            dsum[di] += del[di];
#pragma unroll
            for (int j = 0; j < 8; j++) {
                float e = ex2f(del[di] * Ae[di][j]);
                s[di][j] = fmaf(e, s[di][j], del[di] * buv[j]);
            }
        }
    }

#pragma unroll
    for (int di = 0; di < 2; di++) {
        float P[8];
#pragma unroll
        for (int j = 0; j < 8; j++)
            P[j] = ex2f(dsum[di] * Ae[di][j]);
        const size_t o = ((size_t)((b * NC + c) * 256 + d0 + di)) * 256 + nb;
        *(float4*)(g_P  + o)     = *(float4*)&P[0];
        *(float4*)(g_P  + o + 4) = *(float4*)&P[4];
        *(float4*)(g_Sf + o)     = *(float4*)&s[di][0];
        *(float4*)(g_Sf + o + 4) = *(float4*)&s[di][4];
    }
}

// ---------------------------------------------------------------------------
// Scan pass 2 (fused chunk-summary prologue). Each WARP handles 2 d's.
// Zero-register L1 prefetch of next-step bu/cv rows; 6-shfl reduction;
// lanes 0/16 store y*silu(z) for d0/d0+1.
// ---------------------------------------------------------------------------
__global__ __launch_bounds__(128, 8)
void scan_p2(const float* __restrict__ A)
{
    const int warp = threadIdx.x >> 5;
    const int lane = threadIdx.x & 31;
    int bid = blockIdx.x;                  // ((c*BATCH + b)*32 + dblk)
    const int dblk = bid & 31;  bid >>= 5;
    const int b    = bid & 3;   bid >>= 2;
    const int c    = bid;                  // 0 .. NC-1
    const int d0   = (dblk * 4 + warp) * 2;
    const int nb   = lane << 3;

    float Ae[2][8];
#pragma unroll
    for (int di = 0; di < 2; di++)
#pragma unroll
        for (int j = 0; j < 8; j++)
            Ae[di][j] = A[(d0 + di) * 256 + nb + j] * LOG2E;

    // Reconstruct initial states from chunks 0..c-1 (L2-resident, overlapped)
    float s[2][8];
#pragma unroll
    for (int di = 0; di < 2; di++)
#pragma unroll
        for (int j = 0; j < 8; j++) s[di][j] = 0.f;
    for (int cc = 0; cc < c; cc++) {
#pragma unroll
        for (int di = 0; di < 2; di++) {
            const size_t o = ((size_t)((b * NC + cc) * 256 + d0 + di)) * 256 + nb;
            float P[8], Sf[8];
            *(float4*)&P[0]  = *(const float4*)(g_P  + o);
            *(float4*)&P[4]  = *(const float4*)(g_P  + o + 4);
            *(float4*)&Sf[0] = *(const float4*)(g_Sf + o);
            *(float4*)&Sf[4] = *(const float4*)(g_Sf + o + 4);
#pragma unroll
            for (int j = 0; j < 8; j++)
                s[di][j] = fmaf(P[j], s[di][j], Sf[j]);
        }
    }

    const int base = b * LENGTH * 256;
    const float* __restrict__ bu  = g_bu    + base;
    const float* __restrict__ Cp  = g_Cv    + base;
    const float* __restrict__ dp  = g_delta + base;
    const float* __restrict__ szp = g_sz    + base;
    float*       __restrict__ yp  = g_y     + base;

    const int t0 = c * TC, t1 = t0 + TC;
    pfL1(bu + t0 * 256 + nb);                        // warm first rows
    pfL1(Cp + t0 * 256 + nb);
    for (int t = t0; t < t1; t++) {
        if (t + 1 < t1) {                            // prefetch next rows
            pfL1(bu + (t + 1) * 256 + nb);
            pfL1(Cp + (t + 1) * 256 + nb);
        }
        float2 d2 = *(const float2*)(dp + t * 256 + d0);
        float del[2] = {d2.x, d2.y};
        float buv[8], cv[8];
        *(float4*)&buv[0] = *(const float4*)(bu + t * 256 + nb);
        *(float4*)&buv[4] = *(const float4*)(bu + t * 256 + nb + 4);
        *(float4*)&cv[0]  = *(const float4*)(Cp + t * 256 + nb);
        *(float4*)&cv[4]  = *(const float4*)(Cp + t * 256 + nb + 4);

        float y[2];
#pragma unroll
        for (int di = 0; di < 2; di++) {
            float yacc = 0.f;
#pragma unroll
            for (int j = 0; j < 8; j++) {
                float e = ex2f(del[di] * Ae[di][j]);
                s[di][j] = fmaf(e, s[di][j], del[di] * buv[j]);
                yacc = fmaf(s[di][j], cv[j], yacc);
            }
            y[di] = yacc;
        }

        // 6-shfl reduction: xor16 both -> halves own one d each -> xor8/4/2/1
        y[0] += __shfl_xor_sync(0xffffffffu, y[0], 16);
        y[1] += __shfl_xor_sync(0xffffffffu, y[1], 16);
        float v = (lane < 16) ? y[0] : y[1];
        v += __shfl_xor_sync(0xffffffffu, v, 8);
        v += __shfl_xor_sync(0xffffffffu, v, 4);
        v += __shfl_xor_sync(0xffffffffu, v, 2);
        v += __shfl_xor_sync(0xffffffffu, v, 1);
        // lane 0 holds y[d0], lane 16 holds y[d0+1] — store directly
        if (lane == 0)
            yp[t * 256 + d0]     = v * szp[t * 256 + d0];
        if (lane == 16)
            yp[t * 256 + d0 + 1] = v * szp[t * 256 + d0 + 1];
    }
}

// ---------------------------------------------------------------------------
// Inputs (metadata order): x, W_in, W_delta, W_B, W_C, W_out, A, D(unused)
// ---------------------------------------------------------------------------
extern "C" void kernel_launch(void* const* d_in, const int* in_sizes, int n_in,
                              void* d_out, int out_size)
{
    const float* x       = (const float*)d_in[0];
    const float* W_in    = (const float*)d_in[1];
    const float* W_delta = (const float*)d_in[2];
    const float* W_B     = (const float*)d_in[3];
    const float* W_C     = (const float*)d_in[4];
    const float* W_out   = (const float*)d_in[5];
    const float* A       = (const float*)d_in[6];
    float* out = (float*)d_out;

    // 1) in_proj + split + silu(z)
    gemm_kernel<0><<<dim3(8, 64), 128>>>(x, W_in, nullptr, nullptr, nullptr);
    // 2) delta / bu / Cv projections (fused triple GEMM)
    gemm_kernel<1><<<dim3(12, 64), 128>>>(nullptr, W_delta, W_B, W_C, nullptr);
    // 3) chunked selective scan (R7 structure + L1 prefetch)
    scan_p1<<<(NC - 1) * BATCH * 32, 128>>>(A);
    scan_p2<<<NC * BATCH * 32, 128>>>(A);
    // 4) out_proj
    gemm_kernel<2><<<dim3(2, 64), 128>>>(nullptr, W_out, nullptr, nullptr, out);
}

// round 15
// speedup vs baseline: 1.1650x; 1.1491x over previous
#include <cuda_runtime.h>
#include <cuda_bf16.h>

// Problem constants
#define BATCH   4
#define LENGTH  512
#define DMODEL  128
#define DINNER  256
#define DSTATE  256
#define MROWS   (BATCH * LENGTH)        // 2048
#define LOG2E   1.4426950408889634f
#define NC      16                      // scan chunks
#define TC      32                      // steps per chunk (NC*TC == LENGTH)
#define TB      4                       // y-reduction batch (steps)

// Scratch (allocation-free: __device__ globals)
__device__ float g_xs[MROWS * DINNER];     // xs (first half of in_proj)
__device__ float g_sz[MROWS * DINNER];     // silu(z)
__device__ float g_delta[MROWS * DINNER];  // xs @ W_delta
__device__ float g_bu[MROWS * DSTATE];     // (xs @ W_B) * xs   (elementwise)
__device__ float g_Cv[MROWS * DINNER];     // xs @ W_C
__device__ float g_y[MROWS * DINNER];      // scan output * silu(z)

// Chunked-scan intermediates: layout [((b*NC + c)*256 + d)*256 + n]
__device__ float g_P  [BATCH * NC * DINNER * DSTATE];  // per-chunk prod of a_t
__device__ float g_Sf [BATCH * NC * DINNER * DSTATE];  // per-chunk local final state

__device__ __forceinline__ float ex2f(float x) {
    float e; asm("ex2.approx.ftz.f32 %0, %1;" : "=f"(e) : "f"(x)); return e;
}

// ---------------------------------------------------------------------------
// Tiled fp32 GEMM: C tile 32x64 per block, 128 threads, thread tile 4x4.
// ---------------------------------------------------------------------------
template <int MODE>
__global__ __launch_bounds__(128)
void gemm_kernel(const float* __restrict__ Ag_,
                 const float* __restrict__ B0,
                 const float* __restrict__ B1,
                 const float* __restrict__ B2,
                 float* __restrict__ Og)
{
    constexpr int K   = (MODE == 0) ? 128 : 256;
    constexpr int LDB = (MODE == 0) ? 512 : ((MODE == 1) ? 256 : 128);

    __shared__ float As[16][36];
    __shared__ float Bs[16][68];

    const int tid = threadIdx.x;
    const int tx  = tid & 15;
    const int ty  = tid >> 4;
    const int m0  = blockIdx.y * 32;

    const float* Ag;
    const float* Bg;
    int n0;
    int which = 0;
    if (MODE == 1) {
        which = blockIdx.x >> 2;              // 0: W_delta, 1: W_B, 2: W_C
        n0 = (blockIdx.x & 3) * 64;
        Bg = (which == 0) ? B0 : ((which == 1) ? B1 : B2);
        Ag = g_xs;
    } else {
        n0 = blockIdx.x * 64;
        Bg = B0;
        Ag = (MODE == 0) ? Ag_ : g_y;
    }

    const int aRow  = tid >> 2;
    const int aC4   = (tid & 3) << 2;
    const int bRowk = tid >> 4;
    const int bC4   = (tid & 15) << 2;

    float4 aR;
    float4 bR[2];
    aR = *(const float4*)(Ag + (size_t)(m0 + aRow) * K + aC4);
#pragma unroll
    for (int r = 0; r < 2; r++)
        bR[r] = *(const float4*)(Bg + (size_t)(bRowk + r * 8) * LDB + n0 + bC4);

    float acc[4][4];
#pragma unroll
    for (int i = 0; i < 4; i++)
#pragma unroll
        for (int j = 0; j < 4; j++) acc[i][j] = 0.f;

    for (int k0 = 0; k0 < K; k0 += 16) {
        As[aC4 + 0][aRow] = aR.x;
        As[aC4 + 1][aRow] = aR.y;
        As[aC4 + 2][aRow] = aR.z;
        As[aC4 + 3][aRow] = aR.w;
#pragma unroll
        for (int r = 0; r < 2; r++)
            *(float4*)&Bs[bRowk + r * 8][bC4] = bR[r];
        __syncthreads();

        if (k0 + 16 < K) {
            aR = *(const float4*)(Ag + (size_t)(m0 + aRow) * K + (k0 + 16) + aC4);
#pragma unroll
            for (int r = 0; r < 2; r++)
                bR[r] = *(const float4*)(Bg + (size_t)(k0 + 16 + bRowk + r * 8) * LDB + n0 + bC4);
        }

#pragma unroll
        for (int kk = 0; kk < 16; kk++) {
            float4 av = *(const float4*)&As[kk][ty * 4];
            float4 bv = *(const float4*)&Bs[kk][tx * 4];
            float a[4] = {av.x, av.y, av.z, av.w};
            float b[4] = {bv.x, bv.y, bv.z, bv.w};
#pragma unroll
            for (int i = 0; i < 4; i++)
#pragma unroll
                for (int j = 0; j < 4; j++)
                    acc[i][j] = fmaf(a[i], b[j], acc[i][j]);
        }
        __syncthreads();
    }

#pragma unroll
    for (int i = 0; i < 4; i++) {
        int m = m0 + ty * 4 + i;
#pragma unroll
        for (int j = 0; j < 4; j++) {
            int c = n0 + tx * 4 + j;
            float v = acc[i][j];
            if (MODE == 0) {
                if (c < 256) {
                    g_xs[m * 256 + c] = v;
                } else {
                    float sig = 1.f / (1.f + __expf(-v));
                    g_sz[m * 256 + (c - 256)] = v * sig;   // silu(z)
                }
            } else if (MODE == 1) {
                if (which == 0)      g_delta[m * 256 + c] = v;
                else if (which == 1) g_bu[m * 256 + c] = v * g_xs[m * 256 + c];
                else                 g_Cv[m * 256 + c] = v;
            } else {
                Og[m * 128 + c] = v;
            }
        }
    }
}

// ---------------------------------------------------------------------------
// Scan pass 1: chunks 0..NC-2. Each WARP handles 2 consecutive d's.
// (R7-exact: no prefetch, no reduction — already near its pipe floor.)
//   Sf = local final state (zero-init recurrence)
//   P  = exp2(Ae * sum_chunk delta)
// ---------------------------------------------------------------------------
__global__ __launch_bounds__(128, 8)
void scan_p1(const float* __restrict__ A)
{
    const int warp = threadIdx.x >> 5;
    const int lane = threadIdx.x & 31;
    int bid = blockIdx.x;                  // ((c*BATCH + b)*32 + dblk)
    const int dblk = bid & 31;  bid >>= 5;
    const int b    = bid & 3;   bid >>= 2;
    const int c    = bid;                  // 0 .. NC-2
    const int d0   = (dblk * 4 + warp) * 2;
    const int nb   = lane << 3;

    float Ae[2][8];
#pragma unroll
    for (int di = 0; di < 2; di++)
#pragma unroll
        for (int j = 0; j < 8; j++)
            Ae[di][j] = A[(d0 + di) * 256 + nb + j] * LOG2E;

    const int base = b * LENGTH * 256;
    const float* __restrict__ bu = g_bu    + base;
    const float* __restrict__ dp = g_delta + base;

    float s[2][8], dsum[2];
#pragma unroll
    for (int di = 0; di < 2; di++) {
        dsum[di] = 0.f;
#pragma unroll
        for (int j = 0; j < 8; j++) s[di][j] = 0.f;
    }

    const int t0 = c * TC;
    for (int t = t0; t < t0 + TC; t++) {
        float2 d2 = *(const float2*)(dp + t * 256 + d0);
        float del[2] = {d2.x, d2.y};
        float buv[8];
        *(float4*)&buv[0] = *(const float4*)(bu + t * 256 + nb);
        *(float4*)&buv[4] = *(const float4*)(bu + t * 256 + nb + 4);
#pragma unroll
        for (int di = 0; di < 2; di++) {
            dsum[di] += del[di];
#pragma unroll
            for (int j = 0; j < 8; j++) {
                float e = ex2f(del[di] * Ae[di][j]);
                s[di][j] = fmaf(e, s[di][j], del[di] * buv[j]);
            }
        }
    }

#pragma unroll
    for (int di = 0; di < 2; di++) {
        float P[8];
#pragma unroll
        for (int j = 0; j < 8; j++)
            P[j] = ex2f(dsum[di] * Ae[di][j]);
        const size_t o = ((size_t)((b * NC + c) * 256 + d0 + di)) * 256 + nb;
        *(float4*)(g_P  + o)     = *(float4*)&P[0];
        *(float4*)(g_P  + o + 4) = *(float4*)&P[4];
        *(float4*)(g_Sf + o)     = *(float4*)&s[di][0];
        *(float4*)(g_Sf + o + 4) = *(float4*)&s[di][4];
    }
}

// ---------------------------------------------------------------------------
// Scan pass 2 (fused chunk-summary prologue). Each WARP handles 2 d's.
// y-reductions BATCHED over TB=4 steps: 8 partials (4 t x 2 d) reduced in one
// 5-level butterfly with 4-8x ILP -> shfl-chain latency per step drops ~4x
// (the diagnosed in-order-issue bottleneck). Lanes 0-3 / 16-19 store the
// batch's outputs for d0 / d0+1.
// ---------------------------------------------------------------------------
__global__ __launch_bounds__(128, 7)
void scan_p2(const float* __restrict__ A)
{
    const int warp = threadIdx.x >> 5;
    const int lane = threadIdx.x & 31;
    int bid = blockIdx.x;                  // ((c*BATCH + b)*32 + dblk)
    const int dblk = bid & 31;  bid >>= 5;
    const int b    = bid & 3;   bid >>= 2;
    const int c    = bid;                  // 0 .. NC-1
    const int d0   = (dblk * 4 + warp) * 2;
    const int nb   = lane << 3;

    float Ae[2][8];
#pragma unroll
    for (int di = 0; di < 2; di++)
#pragma unroll
        for (int j = 0; j < 8; j++)
            Ae[di][j] = A[(d0 + di) * 256 + nb + j] * LOG2E;

    // Reconstruct initial states from chunks 0..c-1 (L2-resident, overlapped)
    float s[2][8];
#pragma unroll
    for (int di = 0; di < 2; di++)
#pragma unroll
        for (int j = 0; j < 8; j++) s[di][j] = 0.f;
    for (int cc = 0; cc < c; cc++) {
#pragma unroll
        for (int di = 0; di < 2; di++) {
            const size_t o = ((size_t)((b * NC + cc) * 256 + d0 + di)) * 256 + nb;
            float P[8], Sf[8];
            *(float4*)&P[0]  = *(const float4*)(g_P  + o);
            *(float4*)&P[4]  = *(const float4*)(g_P  + o + 4);
            *(float4*)&Sf[0] = *(const float4*)(g_Sf + o);
            *(float4*)&Sf[4] = *(const float4*)(g_Sf + o + 4);
#pragma unroll
            for (int j = 0; j < 8; j++)
                s[di][j] = fmaf(P[j], s[di][j], Sf[j]);
        }
    }

    const int base = b * LENGTH * 256;
    const float* __restrict__ bu  = g_bu    + base;
    const float* __restrict__ Cp  = g_Cv    + base;
    const float* __restrict__ dp  = g_delta + base;
    const float* __restrict__ szp = g_sz    + base;
    float*       __restrict__ yp  = g_y     + base;

    const int t0 = c * TC;
    for (int tb = t0; tb < t0 + TC; tb += TB) {
        float yv[2 * TB];   // yv[ti*2 + di]

#pragma unroll
        for (int ti = 0; ti < TB; ti++) {
            const int t = tb + ti;
            float2 d2 = *(const float2*)(dp + t * 256 + d0);
            float del[2] = {d2.x, d2.y};
            float buv[8], cv[8];
            *(float4*)&buv[0] = *(const float4*)(bu + t * 256 + nb);
            *(float4*)&buv[4] = *(const float4*)(bu + t * 256 + nb + 4);
            *(float4*)&cv[0]  = *(const float4*)(Cp + t * 256 + nb);
            *(float4*)&cv[4]  = *(const float4*)(Cp + t * 256 + nb + 4);
#pragma unroll
            for (int di = 0; di < 2; di++) {
                float yacc = 0.f;
#pragma unroll
                for (int j = 0; j < 8; j++) {
                    float e = ex2f(del[di] * Ae[di][j]);
                    s[di][j] = fmaf(e, s[di][j], del[di] * buv[j]);
                    yacc = fmaf(s[di][j], cv[j], yacc);
                }
                yv[ti * 2 + di] = yacc;
            }
        }

        // Batched reduction: level 1 = xor16 on all 8 partials (parallel)
#pragma unroll
        for (int k = 0; k < 2 * TB; k++)
            yv[k] += __shfl_xor_sync(0xffffffffu, yv[k], 16);
        // half-select: lanes 0-15 reduce d0's 4 values, lanes 16-31 d1's
        float w[TB];
#pragma unroll
        for (int ti = 0; ti < TB; ti++)
            w[ti] = (lane < 16) ? yv[ti * 2] : yv[ti * 2 + 1];
        // 4 more rounds, 4-way ILP (xor 8/4/2/1 stay within each half)
#pragma unroll
        for (int m = 8; m >= 1; m >>= 1)
#pragma unroll
            for (int ti = 0; ti < TB; ti++)
                w[ti] += __shfl_xor_sync(0xffffffffu, w[ti], m);
        // lanes 0..3 hold d0 totals for t=tb..tb+3; lanes 16..19 hold d0+1's
        if (lane < TB)
            yp[(tb + lane) * 256 + d0] = w[lane] * szp[(tb + lane) * 256 + d0];
        else if (lane >= 16 && lane < 16 + TB) {
            const int ti = lane - 16;
            yp[(tb + ti) * 256 + d0 + 1] = w[ti] * szp[(tb + ti) * 256 + d0 + 1];
        }
    }
}

// ---------------------------------------------------------------------------
// Inputs (metadata order): x, W_in, W_delta, W_B, W_C, W_out, A, D(unused)
// ---------------------------------------------------------------------------
extern "C" void kernel_launch(void* const* d_in, const int* in_sizes, int n_in,
                              void* d_out, int out_size)
{
    const float* x       = (const float*)d_in[0];
    const float* W_in    = (const float*)d_in[1];
    const float* W_delta = (const float*)d_in[2];
    const float* W_B     = (const float*)d_in[3];
    const float* W_C     = (const float*)d_in[4];
    const float* W_out   = (const float*)d_in[5];
    const float* A       = (const float*)d_in[6];
    float* out = (float*)d_out;

    // 1) in_proj + split + silu(z)
    gemm_kernel<0><<<dim3(8, 64), 128>>>(x, W_in, nullptr, nullptr, nullptr);
    // 2) delta / bu / Cv projections (fused triple GEMM)
    gemm_kernel<1><<<dim3(12, 64), 128>>>(nullptr, W_delta, W_B, W_C, nullptr);
    // 3) chunked selective scan (R7 structure; p2 with batched reductions)
    scan_p1<<<(NC - 1) * BATCH * 32, 128>>>(A);
    scan_p2<<<NC * BATCH * 32, 128>>>(A);
    // 4) out_proj
    gemm_kernel<2><<<dim3(2, 64), 128>>>(nullptr, W_out, nullptr, nullptr, out);
}

// round 16
// speedup vs baseline: 1.2490x; 1.0721x over previous
#include <cuda_runtime.h>
#include <cuda_bf16.h>
#include <cuda_fp16.h>

// Problem constants
#define BATCH   4
#define LENGTH  512
#define DMODEL  128
#define DINNER  256
#define DSTATE  256
#define MROWS   (BATCH * LENGTH)        // 2048
#define LOG2E   1.4426950408889634f
#define NC      16                      // scan chunks
#define TC      32                      // steps per chunk (NC*TC == LENGTH)
#define TB      4                       // y-reduction batch (steps)

// Scratch (allocation-free: __device__ globals)
__device__ float  g_xs[MROWS * DINNER];    // xs (first half of in_proj)
__device__ float  g_sz[MROWS * DINNER];    // silu(z)
__device__ float  g_delta[MROWS * DINNER]; // xs @ W_delta
__device__ __half g_buh[MROWS * DSTATE];   // fp16: (xs @ W_B) * xs
__device__ __half g_cvh[MROWS * DINNER];   // fp16: xs @ W_C
__device__ float  g_y[MROWS * DINNER];     // scan output * silu(z)

// Chunked-scan intermediates: layout [((b*NC + c)*256 + d)*256 + n]  (fp32)
__device__ float g_P  [BATCH * NC * DINNER * DSTATE];  // per-chunk prod of a_t
__device__ float g_Sf [BATCH * NC * DINNER * DSTATE];  // per-chunk local final state

__device__ __forceinline__ float ex2f(float x) {
    float e; asm("ex2.approx.ftz.f32 %0, %1;" : "=f"(e) : "f"(x)); return e;
}
// Load 8 consecutive fp16 values (16B, one LDG.128) and widen to fp32.
__device__ __forceinline__ void ld8h(const __half* p, float* out) {
    uint4 raw = *(const uint4*)p;
    const __half2* h2 = reinterpret_cast<const __half2*>(&raw);
#pragma unroll
    for (int k = 0; k < 4; k++) {
        float2 f = __half22float2(h2[k]);
        out[2 * k]     = f.x;
        out[2 * k + 1] = f.y;
    }
}

// ---------------------------------------------------------------------------
// Tiled fp32 GEMM: C tile 32x64 per block, 128 threads, thread tile 4x4.
// ---------------------------------------------------------------------------
template <int MODE>
__global__ __launch_bounds__(128)
void gemm_kernel(const float* __restrict__ Ag_,
                 const float* __restrict__ B0,
                 const float* __restrict__ B1,
                 const float* __restrict__ B2,
                 float* __restrict__ Og)
{
    constexpr int K   = (MODE == 0) ? 128 : 256;
    constexpr int LDB = (MODE == 0) ? 512 : ((MODE == 1) ? 256 : 128);

    __shared__ float As[16][36];
    __shared__ float Bs[16][68];

    const int tid = threadIdx.x;
    const int tx  = tid & 15;
    const int ty  = tid >> 4;
    const int m0  = blockIdx.y * 32;

    const float* Ag;
    const float* Bg;
    int n0;
    int which = 0;
    if (MODE == 1) {
        which = blockIdx.x >> 2;              // 0: W_delta, 1: W_B, 2: W_C
        n0 = (blockIdx.x & 3) * 64;
        Bg = (which == 0) ? B0 : ((which == 1) ? B1 : B2);
        Ag = g_xs;
    } else {
        n0 = blockIdx.x * 64;
        Bg = B0;
        Ag = (MODE == 0) ? Ag_ : g_y;
    }

    const int aRow  = tid >> 2;
    const int aC4   = (tid & 3) << 2;
    const int bRowk = tid >> 4;
    const int bC4   = (tid & 15) << 2;

    float4 aR;
    float4 bR[2];
    aR = *(const float4*)(Ag + (size_t)(m0 + aRow) * K + aC4);
#pragma unroll
    for (int r = 0; r < 2; r++)
        bR[r] = *(const float4*)(Bg + (size_t)(bRowk + r * 8) * LDB + n0 + bC4);

    float acc[4][4];
#pragma unroll
    for (int i = 0; i < 4; i++)
#pragma unroll
        for (int j = 0; j < 4; j++) acc[i][j] = 0.f;

    for (int k0 = 0; k0 < K; k0 += 16) {
        As[aC4 + 0][aRow] = aR.x;
        As[aC4 + 1][aRow] = aR.y;
        As[aC4 + 2][aRow] = aR.z;
        As[aC4 + 3][aRow] = aR.w;
#pragma unroll
        for (int r = 0; r < 2; r++)
            *(float4*)&Bs[bRowk + r * 8][bC4] = bR[r];
        __syncthreads();

        if (k0 + 16 < K) {
            aR = *(const float4*)(Ag + (size_t)(m0 + aRow) * K + (k0 + 16) + aC4);
#pragma unroll
            for (int r = 0; r < 2; r++)
                bR[r] = *(const float4*)(Bg + (size_t)(k0 + 16 + bRowk + r * 8) * LDB + n0 + bC4);
        }

#pragma unroll
        for (int kk = 0; kk < 16; kk++) {
            float4 av = *(const float4*)&As[kk][ty * 4];
            float4 bv = *(const float4*)&Bs[kk][tx * 4];
            float a[4] = {av.x, av.y, av.z, av.w};
            float b[4] = {bv.x, bv.y, bv.z, bv.w};
#pragma unroll
            for (int i = 0; i < 4; i++)
#pragma unroll
                for (int j = 0; j < 4; j++)
                    acc[i][j] = fmaf(a[i], b[j], acc[i][j]);
        }
        __syncthreads();
    }

#pragma unroll
    for (int i = 0; i < 4; i++) {
        int m = m0 + ty * 4 + i;
#pragma unroll
        for (int j = 0; j < 4; j++) {
            int c = n0 + tx * 4 + j;
            float v = acc[i][j];
            if (MODE == 0) {
                if (c < 256) {
                    g_xs[m * 256 + c] = v;
                } else {
                    float sig = 1.f / (1.f + __expf(-v));
                    g_sz[m * 256 + (c - 256)] = v * sig;   // silu(z)
                }
            } else if (MODE == 1) {
                if (which == 0)      g_delta[m * 256 + c] = v;
                else if (which == 1) g_buh[m * 256 + c] = __float2half_rn(v * g_xs[m * 256 + c]);
                else                 g_cvh[m * 256 + c] = __float2half_rn(v);
            } else {
                Og[m * 128 + c] = v;
            }
        }
    }
}

// ---------------------------------------------------------------------------
// Scan pass 1: chunks 0..NC-2. Each WARP handles 2 consecutive d's.
// bu loaded as fp16 (one 16B LDG per lane) and widened in registers.
//   Sf = local final state (zero-init recurrence)
//   P  = exp2(Ae * sum_chunk delta)
// ---------------------------------------------------------------------------
__global__ __launch_bounds__(128, 8)
void scan_p1(const float* __restrict__ A)
{
    const int warp = threadIdx.x >> 5;
    const int lane = threadIdx.x & 31;
    int bid = blockIdx.x;                  // ((c*BATCH + b)*32 + dblk)
    const int dblk = bid & 31;  bid >>= 5;
    const int b    = bid & 3;   bid >>= 2;
    const int c    = bid;                  // 0 .. NC-2
    const int d0   = (dblk * 4 + warp) * 2;
    const int nb   = lane << 3;

    float Ae[2][8];
#pragma unroll
    for (int di = 0; di < 2; di++)
#pragma unroll
        for (int j = 0; j < 8; j++)
            Ae[di][j] = A[(d0 + di) * 256 + nb + j] * LOG2E;

    const int base = b * LENGTH * 256;
    const __half* __restrict__ buh = g_buh   + base;
    const float*  __restrict__ dp  = g_delta + base;

    float s[2][8], dsum[2];
#pragma unroll
    for (int di = 0; di < 2; di++) {
        dsum[di] = 0.f;
#pragma unroll
        for (int j = 0; j < 8; j++) s[di][j] = 0.f;
    }

    const int t0 = c * TC;
    for (int t = t0; t < t0 + TC; t++) {
        float2 d2 = *(const float2*)(dp + t * 256 + d0);
        float del[2] = {d2.x, d2.y};
        float buv[8];
        ld8h(buh + t * 256 + nb, buv);
#pragma unroll
        for (int di = 0; di < 2; di++) {
            dsum[di] += del[di];
#pragma unroll
            for (int j = 0; j < 8; j++) {
                float e = ex2f(del[di] * Ae[di][j]);
                s[di][j] = fmaf(e, s[di][j], del[di] * buv[j]);
            }
        }
    }

#pragma unroll
    for (int di = 0; di < 2; di++) {
        float P[8];
#pragma unroll
        for (int j = 0; j < 8; j++)
            P[j] = ex2f(dsum[di] * Ae[di][j]);
        const size_t o = ((size_t)((b * NC + c) * 256 + d0 + di)) * 256 + nb;
        *(float4*)(g_P  + o)     = *(float4*)&P[0];
        *(float4*)(g_P  + o + 4) = *(float4*)&P[4];
        *(float4*)(g_Sf + o)     = *(float4*)&s[di][0];
        *(float4*)(g_Sf + o + 4) = *(float4*)&s[di][4];
    }
}

// ---------------------------------------------------------------------------
// Scan pass 2 (fused chunk-summary prologue; TB-batched y-reductions from
// the R15 win). Each WARP handles 2 d's. bu/cv loaded as fp16: one 16B LDG
// per lane per array per step — L1 wavefronts per step drop ~33% (the
// diagnosed L1-bandwidth bound at 77%).
// ---------------------------------------------------------------------------
__global__ __launch_bounds__(128, 7)
void scan_p2(const float* __restrict__ A)
{
    const int warp = threadIdx.x >> 5;
    const int lane = threadIdx.x & 31;
    int bid = blockIdx.x;                  // ((c*BATCH + b)*32 + dblk)
    const int dblk = bid & 31;  bid >>= 5;
    const int b    = bid & 3;   bid >>= 2;
    const int c    = bid;                  // 0 .. NC-1
    const int d0   = (dblk * 4 + warp) * 2;
    const int nb   = lane << 3;

    float Ae[2][8];
#pragma unroll
    for (int di = 0; di < 2; di++)
#pragma unroll
        for (int j = 0; j < 8; j++)
            Ae[di][j] = A[(d0 + di) * 256 + nb + j] * LOG2E;

    // Reconstruct initial states from chunks 0..c-1 (L2-resident, overlapped)
    float s[2][8];
#pragma unroll
    for (int di = 0; di < 2; di++)
#pragma unroll
        for (int j = 0; j < 8; j++) s[di][j] = 0.f;
    for (int cc = 0; cc < c; cc++) {
#pragma unroll
        for (int di = 0; di < 2; di++) {
            const size_t o = ((size_t)((b * NC + cc) * 256 + d0 + di)) * 256 + nb;
            float P[8], Sf[8];
            *(float4*)&P[0]  = *(const float4*)(g_P  + o);
            *(float4*)&P[4]  = *(const float4*)(g_P  + o + 4);
            *(float4*)&Sf[0] = *(const float4*)(g_Sf + o);
            *(float4*)&Sf[4] = *(const float4*)(g_Sf + o + 4);
#pragma unroll
            for (int j = 0; j < 8; j++)
                s[di][j] = fmaf(P[j], s[di][j], Sf[j]);
        }
    }

    const int base = b * LENGTH * 256;
    const __half* __restrict__ buh = g_buh   + base;
    const __half* __restrict__ cvh = g_cvh   + base;
    const float*  __restrict__ dp  = g_delta + base;
    const float*  __restrict__ szp = g_sz    + base;
    float*        __restrict__ yp  = g_y     + base;

    const int t0 = c * TC;
    for (int tb = t0; tb < t0 + TC; tb += TB) {
        float yv[2 * TB];   // yv[ti*2 + di]

#pragma unroll
        for (int ti = 0; ti < TB; ti++) {
            const int t = tb + ti;
            float2 d2 = *(const float2*)(dp + t * 256 + d0);
            float del[2] = {d2.x, d2.y};
            float buv[8], cv[8];
            ld8h(buh + t * 256 + nb, buv);
            ld8h(cvh + t * 256 + nb, cv);
#pragma unroll
            for (int di = 0; di < 2; di++) {
                float yacc = 0.f;
#pragma unroll
                for (int j = 0; j < 8; j++) {
                    float e = ex2f(del[di] * Ae[di][j]);
                    s[di][j] = fmaf(e, s[di][j], del[di] * buv[j]);
                    yacc = fmaf(s[di][j], cv[j], yacc);
                }
                yv[ti * 2 + di] = yacc;
            }
        }

        // Batched reduction: level 1 = xor16 on all 8 partials (parallel)
#pragma unroll
        for (int k = 0; k < 2 * TB; k++)
            yv[k] += __shfl_xor_sync(0xffffffffu, yv[k], 16);
        // half-select: lanes 0-15 reduce d0's 4 values, lanes 16-31 d1's
        float w[TB];
#pragma unroll
        for (int ti = 0; ti < TB; ti++)
            w[ti] = (lane < 16) ? yv[ti * 2] : yv[ti * 2 + 1];
        // 4 more rounds, 4-way ILP (xor 8/4/2/1 stay within each half)
#pragma unroll
        for (int m = 8; m >= 1; m >>= 1)
#pragma unroll
            for (int ti = 0; ti < TB; ti++)
                w[ti] += __shfl_xor_sync(0xffffffffu, w[ti], m);
        // lanes 0..3 hold d0 totals for t=tb..tb+3; lanes 16..19 hold d0+1's
        if (lane < TB)
            yp[(tb + lane) * 256 + d0] = w[lane] * szp[(tb + lane) * 256 + d0];
        else if (lane >= 16 && lane < 16 + TB) {
            const int ti = lane - 16;
            yp[(tb + ti) * 256 + d0 + 1] = w[ti] * szp[(tb + ti) * 256 + d0 + 1];
        }
    }
}

// ---------------------------------------------------------------------------
// Inputs (metadata order): x, W_in, W_delta, W_B, W_C, W_out, A, D(unused)
// ---------------------------------------------------------------------------
extern "C" void kernel_launch(void* const* d_in, const int* in_sizes, int n_in,
                              void* d_out, int out_size)
{
    const float* x       = (const float*)d_in[0];
    const float* W_in    = (const float*)d_in[1];
    const float* W_delta = (const float*)d_in[2];
    const float* W_B     = (const float*)d_in[3];
    const float* W_C     = (const float*)d_in[4];
    const float* W_out   = (const float*)d_in[5];
    const float* A       = (const float*)d_in[6];
    float* out = (float*)d_out;

    // 1) in_proj + split + silu(z)
    gemm_kernel<0><<<dim3(8, 64), 128>>>(x, W_in, nullptr, nullptr, nullptr);
    // 2) delta / bu / Cv projections (fused triple GEMM; bu/Cv stored fp16)
    gemm_kernel<1><<<dim3(12, 64), 128>>>(nullptr, W_delta, W_B, W_C, nullptr);
    // 3) chunked selective scan (R15 structure; fp16 streaming operands)
    scan_p1<<<(NC - 1) * BATCH * 32, 128>>>(A);
    scan_p2<<<NC * BATCH * 32, 128>>>(A);
    // 4) out_proj
    gemm_kernel<2><<<dim3(2, 64), 128>>>(nullptr, W_out, nullptr, nullptr, out);
}